// round 9
// baseline (speedup 1.0000x reference)
#include <cuda_runtime.h>
#include <cuda_bf16.h>
#include <cstdint>

// Perceive3D: out[b, k*16+c, z, h, w], k in {identity, d/dW, d/dH, d/dD} (Sobel-smoothed, /16),
// replicate padding. Separable: s=[1,2,1], d=[-1,0,1].
//
// R9 == R8 resubmitted (R8 bench hit an infra failure — "device busy" at harness
// init, before any kernel ran; the f32x2 experiment is still unmeasured):
//  - ALL stencil math in packed f32x2 (add/mul/fma.rn.f32x2 via PTX -> FFMA2/FADD2),
//    halving FMA-pipe issue slots (the .x/.y voxel pair is perfect 2-wide SIMD),
//  - grid ordered so the 8 z-chunks of one (h-tile,bc) column are launch-adjacent
//    (z-halo planes + H rows shared in L2 within a wave).

#define ZLEN 8

// ---- packed f32x2 helpers (PTX-only; ptxas never emits FFMA2 from C++) ----
__device__ __forceinline__ unsigned long long F2U(float2 v) {
    unsigned long long u;
    asm("mov.b64 %0, {%1, %2};" : "=l"(u) : "f"(v.x), "f"(v.y));
    return u;
}
__device__ __forceinline__ float2 U2F(unsigned long long u) {
    float2 v;
    asm("mov.b64 {%0, %1}, %2;" : "=f"(v.x), "=f"(v.y) : "l"(u));
    return v;
}
__device__ __forceinline__ float2 f2add(float2 a, float2 b) {
    unsigned long long r;
    asm("add.rn.f32x2 %0, %1, %2;" : "=l"(r) : "l"(F2U(a)), "l"(F2U(b)));
    return U2F(r);
}
__device__ __forceinline__ float2 f2mul(float2 a, float2 b) {
    unsigned long long r;
    asm("mul.rn.f32x2 %0, %1, %2;" : "=l"(r) : "l"(F2U(a)), "l"(F2U(b)));
    return U2F(r);
}
__device__ __forceinline__ float2 f2fma(float2 a, float2 b, float2 c) {
    unsigned long long r;
    asm("fma.rn.f32x2 %0, %1, %2, %3;" : "=l"(r) : "l"(F2U(a)), "l"(F2U(b)), "l"(F2U(c)));
    return U2F(r);
}
__device__ __forceinline__ float2 f2sub(float2 a, float2 b) {
    const float2 neg1 = make_float2(-1.f, -1.f);
    return f2fma(b, neg1, a);        // a - b
}

__global__ __launch_bounds__(256, 6)
void perceive3d_kernel(const float* __restrict__ x, float* __restrict__ out) {
    const int lx = threadIdx.x;            // 0..31 -> W pair (2lx, 2lx+1)
    const int ly = threadIdx.y;            // 0..7  -> H row within tile (1 warp = 1 row)
    const int z0 = blockIdx.x * ZLEN;      // z fastest: chunks of one column launch-adjacent
    const int h  = blockIdx.y * 8 + ly;
    const int bc = blockIdx.z;             // 0..63 = b*16+c
    const int b  = bc >> 4;
    const int c  = bc & 15;

    const size_t cstride = (size_t)64 * 64 * 64;
    const float* __restrict__ xin = x + (size_t)bc * cstride;
    float* __restrict__ out0 = out + ((size_t)(b * 64) + c) * cstride;

    const int hm = (h == 0)  ? 0  : h - 1;
    const int hp = (h == 63) ? 63 : h + 1;
    const int col = 2 * lx;
    const float* __restrict__ rm = xin + hm * 64 + col;
    const float* __restrict__ rc = xin + (size_t)h * 64 + col;
    const float* __restrict__ rp = xin + hp * 64 + col;
    const int line = h * 64 + col;

    const float2 two = make_float2(2.f, 2.f);
    const float2 k16 = make_float2(0.0625f, 0.0625f);
    const bool l0  = (lx == 0);
    const bool l31 = (lx == 31);

    // load the 3 H rows of plane z (z-clamped) for this thread's W pair
    auto loadPlane = [&](int z, float2& vm, float2& vc, float2& vp) {
        int zz = z < 0 ? 0 : (z > 63 ? 63 : z);
        const size_t off = (size_t)zz * 4096;
        vm = *(const float2*)(rm + off);
        vc = *(const float2*)(rc + off);
        vp = *(const float2*)(rp + off);
    };

    // plane stats, vertical-first, packed:
    //   sv = vm + 2vc + vp, dv = vp - vm; one horizontal shuffle pass; neighbor
    //   pairs packed so P/QW/QH are 1-2 f32x2 ops each.
    auto stats = [&](float2 vm, float2 vc, float2 vp,
                     float2& P, float2& QW, float2& QH, float2& CC) {
        float2 sv = f2fma(vc, two, f2add(vm, vp));
        float2 dv = f2sub(vp, vm);
        float svL = __shfl_up_sync(0xffffffffu,  sv.y, 1);   // col-1
        float svR = __shfl_down_sync(0xffffffffu, sv.x, 1);  // col+2
        float dvL = __shfl_up_sync(0xffffffffu,  dv.y, 1);
        float dvR = __shfl_down_sync(0xffffffffu, dv.x, 1);
        if (l0)  { svL = sv.x; dvL = dv.x; }   // replicate at W=0
        if (l31) { svR = sv.y; dvR = dv.y; }   // replicate at W=63
        float2 svLp = make_float2(svL, sv.x),  svRp = make_float2(sv.y, svR);
        float2 dvLp = make_float2(dvL, dv.x),  dvRp = make_float2(dv.y, dvR);
        P  = f2fma(sv, two, f2add(svLp, svRp));
        QW = f2sub(svRp, svLp);
        QH = f2fma(dv, two, f2add(dvLp, dvRp));
        CC = vc;
    };

    // emit all four outputs for plane z
    auto emit = [&](int z, float2 Pp, float2 Pn,
                    float2 Xp, float2 Xc, float2 Xn,
                    float2 Yp, float2 Yc, float2 Yn, float2 Cc) {
        float2 sx = f2mul(f2fma(Xc, two, f2add(Xp, Xn)), k16);
        float2 sy = f2mul(f2fma(Yc, two, f2add(Yp, Yn)), k16);
        float2 sz = f2mul(f2sub(Pn, Pp), k16);
        const size_t o = (size_t)z * 4096 + line;
        __stcs((float2*)(out0 + o),                Cc);
        __stcs((float2*)(out0 + o + 16 * cstride), sx);
        __stcs((float2*)(out0 + o + 32 * cstride), sy);
        __stcs((float2*)(out0 + o + 48 * cstride), sz);
    };

    float2 Am, Ac, Ap, Bm, Bc, Bp;                       // raw plane double buffer
    float2 Pp, Pc, Pn, Xp, Xc, Xn, Yp, Yc, Yn, Cc, Cn;   // z stat rotation

    // prologue: planes z0-1, z0 -> stats; plane z0+1 staged in A
    loadPlane(z0 - 1, Am, Ac, Ap);
    stats(Am, Ac, Ap, Pp, Xp, Yp, Cn);
    loadPlane(z0, Am, Ac, Ap);
    stats(Am, Ac, Ap, Pc, Xc, Yc, Cc);
    loadPlane(z0 + 1, Am, Ac, Ap);

    #pragma unroll
    for (int t = 0; t < ZLEN; t += 2) {
        // even step: prefetch z+2 into B, consume A (= plane z+1)
        loadPlane(z0 + t + 2, Bm, Bc, Bp);
        stats(Am, Ac, Ap, Pn, Xn, Yn, Cn);
        emit(z0 + t, Pp, Pn, Xp, Xc, Xn, Yp, Yc, Yn, Cc);
        Pp = Pc; Pc = Pn;  Xp = Xc; Xc = Xn;  Yp = Yc; Yc = Yn;  Cc = Cn;

        // odd step: prefetch z+3 into A, consume B (= plane z+2)
        loadPlane(z0 + t + 3, Am, Ac, Ap);
        stats(Bm, Bc, Bp, Pn, Xn, Yn, Cn);
        emit(z0 + t + 1, Pp, Pn, Xp, Xc, Xn, Yp, Yc, Yn, Cc);
        Pp = Pc; Pc = Pn;  Xp = Xc; Xc = Xn;  Yp = Yc; Yc = Yn;  Cc = Cn;
    }
}

extern "C" void kernel_launch(void* const* d_in, const int* in_sizes, int n_in,
                              void* d_out, int out_size) {
    const float* x = (const float*)d_in[0];
    // d_in[1] = kernels (4x3x3x3) — fixed separable stencils folded into the kernel.
    float* out = (float*)d_out;

    dim3 grid(64 / ZLEN, 8, 64);   // (8 z chunks fastest, 8 H tiles, B*C=64) = 4096 blocks
    dim3 block(32, 8);             // 256 threads, warp = one H row
    perceive3d_kernel<<<grid, block>>>(x, out);
}